// round 12
// baseline (speedup 1.0000x reference)
#include <cuda_runtime.h>

// IF neuron: x [T=4, B=32, H=512, W=1024] fp32.
// v=0; for t: v += x[t][i]; s=(v>=1)?1:0; out[t][i]=s; v-=s;
// Pure HBM stream: 256 MB read + 256 MB write (mandatory, irreducible).
//
// FINAL (R6 form — best measured: kernel 76.16us, DRAM 78.3%, 6404 GB/s).
// 256-bit global accesses (ld.global.nc.v8.f32 / st.global.v8.f32) were the
// only lever with measured traction (+2% DRAM). Chunking, cache-policy 2x2,
// occupancy 78->39%, block 256/512, and ordering variants all measured
// neutral (+-1%) — consistent with the chip-wide LTS throughput cap
// (~6300 B/cyc, path-independent), i.e. the hardware ceiling for a 1:1
// read/write mixed stream.

#define T_STEPS 4
#define SPATIAL (32 * 512 * 1024)          // 16,777,216 floats per plane
#define PLANE8  (SPATIAL / 8)              // 2,097,152 float8 per plane
#define THREADS 256
#define BLOCKS  (PLANE8 / THREADS)         // 8192, exact

struct __align__(32) f8 { float v[8]; };

__device__ __forceinline__ f8 ldg256(const float* p) {
    f8 r;
    asm volatile(
        "ld.global.nc.v8.f32 {%0,%1,%2,%3,%4,%5,%6,%7}, [%8];"
        : "=f"(r.v[0]), "=f"(r.v[1]), "=f"(r.v[2]), "=f"(r.v[3]),
          "=f"(r.v[4]), "=f"(r.v[5]), "=f"(r.v[6]), "=f"(r.v[7])
        : "l"(p));
    return r;
}

__device__ __forceinline__ void stg256(float* p, const f8& r) {
    asm volatile(
        "st.global.v8.f32 [%0], {%1,%2,%3,%4,%5,%6,%7,%8};"
        :: "l"(p),
           "f"(r.v[0]), "f"(r.v[1]), "f"(r.v[2]), "f"(r.v[3]),
           "f"(r.v[4]), "f"(r.v[5]), "f"(r.v[6]), "f"(r.v[7])
        : "memory");
}

__global__ __launch_bounds__(THREADS) void if_neuron_kernel(
    const float* __restrict__ x, float* __restrict__ out)
{
    const size_t i8 = blockIdx.x * (size_t)THREADS + threadIdx.x; // float8 idx
    const size_t off = i8 * 8;

    // Front-batched 256-bit loads, one per timestep plane (MLP=4).
    f8 x0 = ldg256(x + 0 * (size_t)SPATIAL + off);
    f8 x1 = ldg256(x + 1 * (size_t)SPATIAL + off);
    f8 x2 = ldg256(x + 2 * (size_t)SPATIAL + off);
    f8 x3 = ldg256(x + 3 * (size_t)SPATIAL + off);

    // IF-neuron scan per element, registers only.
    f8 s0, s1, s2, s3;
#pragma unroll
    for (int k = 0; k < 8; ++k) {
        float v = 0.f, s;
        v += x0.v[k]; s = (v >= 1.0f) ? 1.0f : 0.0f; s0.v[k] = s; v -= s;
        v += x1.v[k]; s = (v >= 1.0f) ? 1.0f : 0.0f; s1.v[k] = s; v -= s;
        v += x2.v[k]; s = (v >= 1.0f) ? 1.0f : 0.0f; s2.v[k] = s; v -= s;
        v += x3.v[k]; s = (v >= 1.0f) ? 1.0f : 0.0f; s3.v[k] = s;
    }

    // Back-batched 256-bit stores.
    stg256(out + 0 * (size_t)SPATIAL + off, s0);
    stg256(out + 1 * (size_t)SPATIAL + off, s1);
    stg256(out + 2 * (size_t)SPATIAL + off, s2);
    stg256(out + 3 * (size_t)SPATIAL + off, s3);
}

extern "C" void kernel_launch(void* const* d_in, const int* in_sizes, int n_in,
                              void* d_out, int out_size)
{
    const float* x = (const float*)d_in[0];
    float* out = (float*)d_out;
    if_neuron_kernel<<<BLOCKS, THREADS>>>(x, out);
}

// round 13
// speedup vs baseline: 1.0023x; 1.0023x over previous
#include <cuda_runtime.h>

// IF neuron: x [T=4, B=32, H=512, W=1024] fp32.
// v=0; for t: v += x[t][i]; s=(v>=1)?1:0; out[t][i]=s; v-=s;
// Pure HBM stream: 256 MB read + 256 MB write (mandatory, irreducible).
// R13: last unmeasured matrix cell — streaming (.cs, evict-first) STORES at
// 256-bit width. Cache-policy sweep was previously done only at 128-bit,
// before width proved to be the sole effective lever. Loads stay .nc.

#define T_STEPS 4
#define SPATIAL (32 * 512 * 1024)          // 16,777,216 floats per plane
#define PLANE8  (SPATIAL / 8)              // 2,097,152 float8 per plane
#define THREADS 256
#define BLOCKS  (PLANE8 / THREADS)         // 8192, exact

struct __align__(32) f8 { float v[8]; };

__device__ __forceinline__ f8 ldg256(const float* p) {
    f8 r;
    asm volatile(
        "ld.global.nc.v8.f32 {%0,%1,%2,%3,%4,%5,%6,%7}, [%8];"
        : "=f"(r.v[0]), "=f"(r.v[1]), "=f"(r.v[2]), "=f"(r.v[3]),
          "=f"(r.v[4]), "=f"(r.v[5]), "=f"(r.v[6]), "=f"(r.v[7])
        : "l"(p));
    return r;
}

__device__ __forceinline__ void stg256cs(float* p, const f8& r) {
    asm volatile(
        "st.global.cs.v8.f32 [%0], {%1,%2,%3,%4,%5,%6,%7,%8};"
        :: "l"(p),
           "f"(r.v[0]), "f"(r.v[1]), "f"(r.v[2]), "f"(r.v[3]),
           "f"(r.v[4]), "f"(r.v[5]), "f"(r.v[6]), "f"(r.v[7])
        : "memory");
}

__global__ __launch_bounds__(THREADS) void if_neuron_kernel(
    const float* __restrict__ x, float* __restrict__ out)
{
    const size_t i8 = blockIdx.x * (size_t)THREADS + threadIdx.x; // float8 idx
    const size_t off = i8 * 8;

    // Front-batched 256-bit non-coherent loads, one per timestep plane.
    f8 x0 = ldg256(x + 0 * (size_t)SPATIAL + off);
    f8 x1 = ldg256(x + 1 * (size_t)SPATIAL + off);
    f8 x2 = ldg256(x + 2 * (size_t)SPATIAL + off);
    f8 x3 = ldg256(x + 3 * (size_t)SPATIAL + off);

    // IF-neuron scan per element, registers only.
    f8 s0, s1, s2, s3;
#pragma unroll
    for (int k = 0; k < 8; ++k) {
        float v = 0.f, s;
        v += x0.v[k]; s = (v >= 1.0f) ? 1.0f : 0.0f; s0.v[k] = s; v -= s;
        v += x1.v[k]; s = (v >= 1.0f) ? 1.0f : 0.0f; s1.v[k] = s; v -= s;
        v += x2.v[k]; s = (v >= 1.0f) ? 1.0f : 0.0f; s2.v[k] = s; v -= s;
        v += x3.v[k]; s = (v >= 1.0f) ? 1.0f : 0.0f; s3.v[k] = s;
    }

    // Back-batched 256-bit streaming (evict-first) stores.
    stg256cs(out + 0 * (size_t)SPATIAL + off, s0);
    stg256cs(out + 1 * (size_t)SPATIAL + off, s1);
    stg256cs(out + 2 * (size_t)SPATIAL + off, s2);
    stg256cs(out + 3 * (size_t)SPATIAL + off, s3);
}

extern "C" void kernel_launch(void* const* d_in, const int* in_sizes, int n_in,
                              void* d_out, int out_size)
{
    const float* x = (const float*)d_in[0];
    float* out = (float*)d_out;
    if_neuron_kernel<<<BLOCKS, THREADS>>>(x, out);
}